// round 16
// baseline (speedup 1.0000x reference)
#include <cuda_runtime.h>
#include <math.h>

#define B_ 32
#define S_ 64
#define T_ 64
#define H_ 256
#define K3 768
#define SOS 1
#define NBLK 128
#define NTHR 256
#define NLINE 32
#define LSTRIDE 64   // 64 u32 = 256B between counter lines

typedef unsigned long long u64;

// pair-packed layout for h/x: element (jj,b) at float index ((jj>>1)*64 + b*2 + (jj&1))
#define HP(jj,b) ((((jj) >> 1) * 64) + ((b) * 2) + ((jj) & 1))

// ---------------- device scratch ----------------
__device__ float g_hT[2][H_ * B_];          // hidden state, pair-packed, double-buffered
__device__ float g_hB[B_ * H_];             // hidden state row-major [b][j]
__device__ float g_xT_all[S_ * H_ * B_];    // encoder inputs [t][jj][b] (scalar layout)
__device__ float g_giE[S_ * K3 * B_];       // precomputed encoder gi [t][k][b]
__device__ float g_xT[H_ * B_];             // decoder x, pair-packed
__device__ float g_EB[B_ * S_ * H_];        // encoder outputs [b][s][j]
__device__ float g_F[B_ * S_ * H_];         // F[b][s][jp] = W_comb2[jp] . enc_outs[s,b]
__device__ float g_c0[H_];
__device__ float g_probs[B_ * T_];
__device__ __align__(128) unsigned int g_bar_count = 0;
__device__ __align__(128) unsigned int g_bar_gen = 0;
__device__ __align__(256) unsigned int g_barA[NLINE * LSTRIDE];
__device__ __align__(256) unsigned int g_xA[NLINE * LSTRIDE];
__device__ __align__(256) unsigned int g_hA[NLINE * LSTRIDE];
__device__ __align__(256) unsigned int g_eA[NLINE * LSTRIDE];

// smem offsets (floats)
#define O_SET   0        // 16640 attn enc_outs TRANSPOSED [jj][s], pitch 65
#define O_SF    16640    // 8192  attn F half
#define O_SH    24832    // 8192  stage (precompute) / sgpH(3072)+sgpI(3072) in loops
#define O_SX    33024    // 8192  stage (precompute) / sgp2(512) in decode (attn)
#define O_SWD   41216    // 6144  dec weights (rows 0-11 gh, 12-23 gi)
#define O_SWE   47360    // 1536  enc weights (6 rows)
#define O_SATT  48896    // 64
#define O_SRED  48960    // 32
#define O_SBH   48992    // 12
#define O_SBI   49004    // 12
#define O_SBE   49016    // 8 (6 used)
#define SMEMF   49024

// fast activations: MUFU-based, error ~1e-6 (budget 1e-3)
__device__ __forceinline__ float fsig(float x) {
    return __fdividef(1.f, 1.f + __expf(-x));
}
__device__ __forceinline__ float ftanh(float x) {
    x = fminf(fmaxf(x, -15.f), 15.f);
    float e2 = __expf(2.f * x);
    return __fdividef(e2 - 1.f, e2 + 1.f);
}

__device__ __forceinline__ float wred(float v) {
#pragma unroll
    for (int o = 16; o > 0; o >>= 1) v += __shfl_xor_sync(0xffffffffu, v, o);
    return v;
}
__device__ __forceinline__ float wmax(float v) {
#pragma unroll
    for (int o = 16; o > 0; o >>= 1) v = fmaxf(v, __shfl_xor_sync(0xffffffffu, v, o));
    return v;
}

// packed fp32x2 FMA: d += a*b elementwise (exact fp32 FMA semantics)
__device__ __forceinline__ void fma2(u64& d, u64 a, u64 b) {
    asm("fma.rn.f32x2 %0, %1, %2, %0;" : "+l"(d) : "l"(a), "l"(b));
}
__device__ __forceinline__ float sum2(u64 v) {
    float x, y;
    asm("mov.b64 {%0,%1}, %2;" : "=f"(x), "=f"(y) : "l"(v));
    return x + y;
}

__device__ __forceinline__ void arrive(unsigned int* arr, int line) {
    asm volatile("red.release.gpu.global.add.u32 [%0], 1;" :: "l"(arr + line * LSTRIDE) : "memory");
}
// executed by FULL warp 0 only: lane l polls line l; relaxed polls + one fence after detect
__device__ __forceinline__ void wait_lines(unsigned int* arr, unsigned int target) {
    if (target == 0) return;
    unsigned int* p = arr + (threadIdx.x & 31) * LSTRIDE;
    for (;;) {
        unsigned int v;
        asm volatile("ld.relaxed.gpu.global.u32 %0, [%1];" : "=r"(v) : "l"(p));
        if (__all_sync(0xffffffffu, (int)(v - target) >= 0)) break;
    }
    asm volatile("fence.acq_rel.gpu;" ::: "memory");
}

// legacy self-cleaning barrier (init phases only; safe across graph replays)
__device__ __forceinline__ void gen_barrier() {
    __syncthreads();
    if (threadIdx.x == 0) {
        unsigned gen;
        asm volatile("ld.acquire.gpu.global.u32 %0, [%1];" : "=r"(gen) : "l"(&g_bar_gen));
        unsigned old;
        asm volatile("atom.release.gpu.global.add.u32 %0, [%1], %2;"
                     : "=r"(old) : "l"(&g_bar_count), "r"(1u) : "memory");
        if (old == NBLK - 1) {
            asm volatile("st.relaxed.gpu.global.u32 [%0], %1;" :: "l"(&g_bar_count), "r"(0u) : "memory");
            asm volatile("st.release.gpu.global.u32 [%0], %1;" :: "l"(&g_bar_gen), "r"(gen + 1u) : "memory");
        } else {
            unsigned cur;
            do { asm volatile("ld.acquire.gpu.global.u32 %0, [%1];" : "=r"(cur) : "l"(&g_bar_gen)); }
            while (cur == gen);
        }
    }
    __syncthreads();
}

// distributed full barrier over all 128 blocks (4 arrivals per line)
__device__ __forceinline__ void dist_barrier(unsigned int nb) {
    __syncthreads();
    if ((threadIdx.x >> 5) == 0) {
        if ((threadIdx.x & 31) == 0) arrive(g_barA, blockIdx.x & 31);
        wait_lines(g_barA, 4u * nb);
    }
    __syncthreads();
}

__device__ __forceinline__ void stage32KB(float* dst, const float* src, int tid) {
    const float4* s4 = (const float4*)src;
    float4* d4 = (float4*)dst;
    for (int i = tid; i < (H_ * B_) / 4; i += NTHR) d4[i] = __ldcg(s4 + i);
}

// legacy dual-row dot for the one-time giE precompute (scalar [jj][b] smem)
__device__ __forceinline__ float2 dot2(const float4* __restrict__ p0, const float4* __restrict__ p1,
                                       const float* __restrict__ sv, int lane, float b0, float b1) {
    float a0a = b0, a0b = 0.f, a1a = b1, a1b = 0.f;
#pragma unroll 8
    for (int q = 0; q < 64; q++) {
        float4 wa = __ldg(p0 + q);
        float4 wb = __ldg(p1 + q);
        int base = q * 128 + lane;
        float h0 = sv[base], h1 = sv[base + 32], h2 = sv[base + 64], h3 = sv[base + 96];
        a0a += wa.x * h0; a0b += wa.y * h1; a0a += wa.z * h2; a0b += wa.w * h3;
        a1a += wb.x * h0; a1b += wb.y * h1; a1a += wb.z * h2; a1b += wb.w * h3;
    }
    return make_float2(a0a + a0b, a1a + a1b);
}

// jj-split dot, packed: warp w owns jj in [w*32, w*32+32); NR rows; lane = b.
template<int NR>
__device__ __forceinline__ void dotGP(const float* __restrict__ sWb,
                                      const float* __restrict__ gsrc,
                                      float* __restrict__ sgp, int w, int lane) {
    const u64* g2 = (const u64*)gsrc;
    u64 hp[16];
#pragma unroll
    for (int i = 0; i < 16; i++) hp[i] = __ldcg(g2 + (w * 16 + i) * 32 + lane);
    const ulonglong2* W2 = (const ulonglong2*)sWb;
    u64 acc[NR];
#pragma unroll
    for (int r = 0; r < NR; r++) acc[r] = 0ull;
#pragma unroll
    for (int r = 0; r < NR; r++) {
#pragma unroll
        for (int q = 0; q < 8; q++) {
            ulonglong2 wv = W2[r * 64 + w * 8 + q];   // broadcast LDS.128
            fma2(acc[r], wv.x, hp[2 * q]);
            fma2(acc[r], wv.y, hp[2 * q + 1]);
        }
    }
#pragma unroll
    for (int r = 0; r < NR; r++) sgp[r * 256 + w * 32 + lane] = sum2(acc[r]);
}

__global__ void __launch_bounds__(NTHR, 1)
seq2seq_kernel(const int* __restrict__ ctx_tok, const int* __restrict__ inp_tok,
               const int* __restrict__ tsamp,
               const float* __restrict__ enc_emb,
               const float* __restrict__ enc_Wih, const float* __restrict__ enc_Whh,
               const float* __restrict__ enc_bih, const float* __restrict__ enc_bhh,
               const float* __restrict__ dec_emb,
               const float* __restrict__ W_comb, const float* __restrict__ b_comb,
               const float* __restrict__ dec_Wih, const float* __restrict__ dec_Whh,
               const float* __restrict__ dec_bih, const float* __restrict__ dec_bhh,
               const float* __restrict__ W_out, const float* __restrict__ b_out,
               float* __restrict__ out)
{
    extern __shared__ float sm[];
    float* sET  = sm + O_SET;       // [jj][s], pitch 65
    float* sF   = sm + O_SF;
    float* sh   = sm + O_SH;        // precompute stage
    float* sgpH = sm + O_SH;        // loop-phase gh partials (3072)
    float* sgpI = sm + O_SH + 3072; // loop-phase gi partials (3072)
    float* sx   = sm + O_SX;
    float* sgp2 = sm + O_SX;        // decode-phase attn score partials (512)
    float* sWd  = sm + O_SWD;
    float* sWe  = sm + O_SWE;
    float* satt = sm + O_SATT;
    float* sred = sm + O_SRED;
    float* sbh  = sm + O_SBH;
    float* sbi  = sm + O_SBI;
    float* sbe  = sm + O_SBE;

    const int tid  = threadIdx.x;
    const int lane = tid & 31;
    const int w    = tid >> 5;       // warp 0..7
    const int bx   = blockIdx.x;

    // ---------------- init (parallel) ----------------
    for (int i = bx * NTHR + tid; i < NLINE * LSTRIDE; i += NBLK * NTHR) {
        g_barA[i] = 0u; g_xA[i] = 0u; g_hA[i] = 0u; g_eA[i] = 0u;
    }
    for (int i = bx * NTHR + tid; i < H_ * B_; i += NBLK * NTHR) g_hT[0][i] = 0.f;

    for (int i = bx * NTHR + tid; i < S_ * B_ * H_; i += NBLK * NTHR) {
        int jj = i & (H_ - 1);
        int tb = i >> 8;
        int b  = tb & (B_ - 1);
        int t  = tb >> 5;
        int tok = ctx_tok[b * S_ + t];
        g_xT_all[(t * H_ + jj) * B_ + b] = enc_emb[(size_t)tok * H_ + jj];
    }
    {   // c0[j'] = b_comb[j'] + W_comb[j', 0:H] . dec_emb[SOS]   (blocks 0..31)
        int gw = bx * 8 + w;
        if (gw < H_) {
            float s = 0.f;
#pragma unroll
            for (int m = 0; m < 8; m++) {
                int jj = lane + 32 * m;
                s += __ldg(&W_comb[(size_t)gw * (2 * H_) + jj]) * __ldg(&dec_emb[SOS * H_ + jj]);
            }
            s = wred(s);
            if (lane == 0) g_c0[gw] = s + b_comb[gw];
        }
    }
    gen_barrier();

    // ---------------- encoder gi precompute (one-time, parallel) ----------------
    {
        const int t  = bx >> 1;
        const int kh = (bx & 1) * 384;
        stage32KB(sh, g_xT_all + (size_t)t * H_ * B_, tid);
        __syncthreads();
        for (int i = 0; i < 24; i++) {
            int k0 = kh + w * 48 + 2 * i;
            int k1 = k0 + 1;
            const float4* pA = (const float4*)(enc_Wih + (size_t)k0 * H_);
            const float4* pB = (const float4*)(enc_Wih + (size_t)k1 * H_);
            float2 r = dot2(pA, pB, sh, lane, enc_bih[k0], enc_bih[k1]);
            g_giE[((size_t)t * K3 + k0) * B_ + lane] = r.x;
            g_giE[((size_t)t * K3 + k1) * B_ + lane] = r.y;
        }
    }
    gen_barrier();

    // ---------------- encoder weight preload (6 rows: r = g*2+p) ----------------
    {
        float4* d = (float4*)sWe;
        for (int i = tid; i < 6 * 64; i += NTHR) {
            int r = i >> 6, q = i & 63;
            int k = (r >> 1) * H_ + bx * 2 + (r & 1);
            d[i] = __ldg(((const float4*)(enc_Whh + (size_t)k * H_)) + q);
        }
        if (tid < 6) sbe[tid] = enc_bhh[(tid >> 1) * H_ + bx * 2 + (tid & 1)];
    }
    __syncthreads();

    int buf = 0;
    float hprevE = 0.f;   // register-carried h_old (encoder, w<2)

    // ---------------- encoder: 64 steps ----------------
    for (int t = 0; t < S_; t++) {
        float gi0 = 0.f, gi1 = 0.f, gi2 = 0.f;
        if (w < 2) {
            const float* gp = g_giE + ((size_t)t * K3 + (bx * 2 + w)) * B_ + lane;
            gi0 = __ldcg(gp);
            gi1 = __ldcg(gp + 256 * B_);
            gi2 = __ldcg(gp + 512 * B_);
        }
        dotGP<6>(sWe, g_hT[buf], sgpH, w, lane);
        __syncthreads();

        if (w < 2) {   // fused reduce + combine: rows w (r), 2+w (z), 4+w (n)
            int j = bx * 2 + w;
            float ghr = sbe[w], ghz = sbe[2 + w], ghn = sbe[4 + w];
#pragma unroll
            for (int u = 0; u < 8; u++) {
                ghr += sgpH[w * 256 + u * 32 + lane];
                ghz += sgpH[(2 + w) * 256 + u * 32 + lane];
                ghn += sgpH[(4 + w) * 256 + u * 32 + lane];
            }
            float r = fsig(gi0 + ghr);
            float z = fsig(gi1 + ghz);
            float n = ftanh(gi2 + r * ghn);
            float hn = (1.f - z) * n + z * hprevE;
            hprevE = hn;
            g_hT[buf ^ 1][HP(j, lane)] = hn;
            g_EB[((size_t)lane * S_ + t) * H_ + j] = hn;
            if (t == S_ - 1) g_hB[lane * H_ + j] = hn;
            __syncwarp();
            if (lane == 0) arrive(g_eA, bx & 31);
        }
        if (w == 0) wait_lines(g_eA, 8u * (unsigned)(t + 1));
        __syncthreads();
        buf ^= 1;
        if (bx >= 64) {   // attn blocks progressively stage enc_outs TRANSPOSED: sET[jj][t]
            int b = (bx - 64) >> 1;
            sET[tid * 65 + t] = __ldcg(&g_EB[((size_t)b * S_ + t) * H_ + tid]);
        }
    }

    // ---------------- F precompute: F[b][s][jp] = W_comb2[jp] . enc_outs[s,b] ----------------
    {
        int jpT = bx & 15, bsT = bx >> 4;
        int jp0 = jpT * 16, p0 = bsT * 256;
        float4* wt = (float4*)sx;   // 16 rows x 64 quads
        for (int i = tid; i < 16 * 64; i += NTHR) {
            int r = i >> 6, q = i & 63;
            wt[i] = __ldg(((const float4*)(W_comb + (size_t)(jp0 + r) * (2 * H_) + H_)) + q);
        }
        __syncthreads();
        int jpl = tid >> 4, pl = tid & 15;
        for (int i = 0; i < 16; i++) {
            int p = p0 + i * 16 + pl;
            int b = p >> 6, s = p & 63;
            const float4* e4 = (const float4*)(g_EB + ((size_t)b * S_ + s) * H_);
            float a0 = 0.f, a1 = 0.f;
#pragma unroll 8
            for (int q = 0; q < 64; q++) {
                float4 e = __ldcg(e4 + q);
                float4 wv = wt[jpl * 64 + q];
                a0 += e.x * wv.x + e.z * wv.z;
                a1 += e.y * wv.y + e.w * wv.w;
            }
            g_F[((size_t)b * S_ + s) * H_ + jp0 + jpl] = a0 + a1;
        }
    }
    gen_barrier();

    // ---------------- decode-phase staging ----------------
    float hprevD = 0.f;
    float c0reg = 0.f;
    if (bx >= 64) {   // attn: stage F half [s][jp_local], cache c0 in register
        int bxa = bx - 64, b = bxa >> 1, half = bxa & 1;
        float4* dst = (float4*)sF;
        for (int i = tid; i < 64 * 32; i += NTHR) {
            int s = i >> 5, q = i & 31;
            dst[i] = __ldcg(((const float4*)(g_F + ((size_t)b * S_ + s) * H_ + half * 128)) + q);
        }
        if (tid < 128) c0reg = __ldg(&g_c0[half * 128 + tid]);
    } else {          // GRU: stage decoder weights (24 rows) + biases, seed hold register
        float4* d = (float4*)sWd;
        for (int i = tid; i < 24 * 64; i += NTHR) {
            int r = i >> 6, q = i & 63;
            int rr = (r < 12) ? r : (r - 12);
            int k = (rr >> 2) * H_ + bx * 4 + (rr & 3);
            const float* src = (r < 12) ? dec_Whh : dec_Wih;
            d[i] = __ldg(((const float4*)(src + (size_t)k * H_)) + q);
        }
        if (tid < 12) {
            int k = (tid >> 2) * H_ + bx * 4 + (tid & 3);
            sbh[tid] = dec_bhh[k];
            sbi[tid] = dec_bih[k];
        }
        if (w < 4) hprevD = __ldcg(&g_hT[0][HP(bx * 4 + w, lane)]);   // h_enc
    }
    __syncthreads();

    // ---------------- decoder: 64 steps, 2 producer flags each ----------------
    for (int t = 0; t < T_; t++) {
        // prob prefetch: W_out row for token t-1, independent of h (overlaps h-wait)
        float wrow[8]; int tokPrev = 0;
        const bool probWarp = (bx >= 64) && (((bx - 64) & 1) == 1) && (w == 4);
        if (probWarp && t > 0) {
            int b = (bx - 64) >> 1;
            tokPrev = __ldg(&inp_tok[b * T_ + (t - 1)]);
#pragma unroll
            for (int m = 0; m < 8; m++) wrow[m] = __ldg(&W_out[(size_t)tokPrev * H_ + lane + 32 * m]);
        }

        if (w == 0) wait_lines(g_hA, 8u * (unsigned)t);
        __syncthreads();

        if (bx < 64) {
            // ---- GRU path ----
            dotGP<12>(sWd, g_hT[buf], sgpH, w, lane);       // gh partials
            if (w == 0) wait_lines(g_xA, 8u * (unsigned)(t + 1));
            __syncthreads();
            dotGP<12>(sWd + 12 * H_, g_xT, sgpI, w, lane);  // gi partials
            __syncthreads();
            if (w < 4) {   // fused reduce + combine: rows w (r), 4+w (z), 8+w (n)
                int j = bx * 4 + w;
                float ghr = sbh[w], ghz = sbh[4 + w], ghn = sbh[8 + w];
                float gir = sbi[w], giz = sbi[4 + w], gin = sbi[8 + w];
#pragma unroll
                for (int u = 0; u < 8; u++) {
                    int o = u * 32 + lane;
                    ghr += sgpH[w * 256 + o];
                    ghz += sgpH[(4 + w) * 256 + o];
                    ghn += sgpH[(8 + w) * 256 + o];
                    gir += sgpI[w * 256 + o];
                    giz += sgpI[(4 + w) * 256 + o];
                    gin += sgpI[(8 + w) * 256 + o];
                }
                float r = fsig(gir + ghr);
                float z = fsig(giz + ghz);
                float n = ftanh(gin + r * ghn);
                float hn = (1.f - z) * n + z * hprevD;
                hprevD = hn;
                g_hT[buf ^ 1][HP(j, lane)] = hn;
                g_hB[lane * H_ + j] = hn;
                __syncwarp();
                if (lane == 0) arrive(g_hA, bx & 31);
            }
        } else {
            // ---- attention path: b = (bx-64)>>1, half = (bx-64)&1 ----
            const int bxa = bx - 64, b = bxa >> 1, half = bxa & 1;
            // transposed scores: warp w owns jj in [32w, 32w+32); lane owns s=lane, s=lane+32
            {
                const int jj0 = w * 32;
                float hval = __ldcg(&g_hB[b * H_ + jj0 + lane]);
                const float* et = sET + jj0 * 65 + lane;
                float p0 = 0.f, p1 = 0.f;
#pragma unroll
                for (int i = 0; i < 32; i++) {
                    float hv = __shfl_sync(0xffffffffu, hval, i);
                    p0 += hv * et[i * 65];
                    p1 += hv * et[i * 65 + 32];
                }
                sgp2[w * 64 + lane] = p0;
                sgp2[w * 64 + 32 + lane] = p1;
            }
            __syncthreads();
            if (w == 0) {   // fused cross-warp reduce + softmax (values in registers)
                float v0 = 0.f, v1 = 0.f;
#pragma unroll
                for (int u = 0; u < 8; u++) { v0 += sgp2[u * 64 + lane]; v1 += sgp2[u * 64 + 32 + lane]; }
                float mx = wmax(fmaxf(v0, v1));
                float e0 = __expf(v0 - mx), e1 = __expf(v1 - mx);
                float rs = __fdividef(1.f, wred(e0 + e1));
                satt[lane] = e0 * rs; satt[lane + 32] = e1 * rs;
            }
            // x warps (0-3) sync with softmax producer via scoped barrier; warps 4-7 skip
            if (tid < 128) {
                asm volatile("bar.sync 1, 128;" ::: "memory");
                int jp = half * 128 + tid;
                const float* fp = sF + tid;
                float a0 = c0reg, a1 = 0.f, a2 = 0.f, a3 = 0.f;
#pragma unroll
                for (int s = 0; s < S_; s += 4) {
                    a0 += satt[s]     * fp[s * 128];
                    a1 += satt[s + 1] * fp[(s + 1) * 128];
                    a2 += satt[s + 2] * fp[(s + 2) * 128];
                    a3 += satt[s + 3] * fp[(s + 3) * 128];
                }
                float acc = (a0 + a1) + (a2 + a3);
                g_xT[HP(jp, b)] = acc > 0.f ? acc : 0.f;
                __syncwarp();
                if (lane == 0) arrive(g_xA, bxa & 31);
            } else if (probWarp && t > 0) {
                // prob for step t-1, fully concurrent with softmax + x compute
                float p = 0.f;
#pragma unroll
                for (int m = 0; m < 8; m++) p += __ldcg(&g_hB[b * H_ + lane + 32 * m]) * wrow[m];
                p = wred(p);
                if (lane == 0) g_probs[b * T_ + (t - 1)] = fsig(p + __ldg(&b_out[tokPrev]));
            }
        }
        buf ^= 1;
    }

    // ---------------- final-step prob ----------------
    if (bx >= 64 && ((bx - 64) & 1) == 1) {
        const int b = (bx - 64) >> 1;
        if (w == 0) {
            wait_lines(g_hA, 8u * (unsigned)T_);
            int tok = __ldg(&inp_tok[b * T_ + (T_ - 1)]);
            float p = 0.f;
#pragma unroll
            for (int m = 0; m < 8; m++)
                p += __ldcg(&g_hB[b * H_ + lane + 32 * m]) * __ldg(&W_out[(size_t)tok * H_ + lane + 32 * m]);
            p = wred(p);
            if (lane == 0) g_probs[b * T_ + (T_ - 1)] = fsig(p + b_out[tok]);
        }
    }
    dist_barrier(1u);

    // ---------------- outputs ----------------
    for (int i = bx * NTHR + tid; i < B_ * T_; i += NBLK * NTHR) out[1 + i] = __ldcg(g_probs + i);
    if (bx == 0) {
        float tv = tsamp ? (float)(*tsamp) : 1.0f;
        float acc = 0.f;
        for (int i = tid; i < B_ * T_; i += NTHR) {
            float p  = __ldcg(g_probs + i);
            float lp = fmaxf(logf(p), -100.f);
            float l1 = fmaxf(log1pf(-p), -100.f);
            acc += tv * lp + (1.f - tv) * l1;
        }
        acc = wred(acc);
        if (lane == 0) sred[w] = acc;
        __syncthreads();
        if (tid == 0) {
            float s = 0.f;
            for (int u = 0; u < 8; u++) s += sred[u];
            out[0] = -s / (float)(B_ * T_);
        }
    }
}

extern "C" void kernel_launch(void* const* d_in, const int* in_sizes, int n_in,
                              void* d_out, int out_size) {
    (void)in_sizes; (void)out_size;
    const size_t smem = SMEMF * sizeof(float);   // 196,096 B
    cudaFuncSetAttribute(seq2seq_kernel, cudaFuncAttributeMaxDynamicSharedMemorySize, (int)smem);

    int base = (n_in >= 17) ? 3 : 2;
    const int* ts = (n_in >= 17) ? (const int*)d_in[2] : nullptr;

    seq2seq_kernel<<<NBLK, NTHR, smem>>>(
        (const int*)d_in[0], (const int*)d_in[1], ts,
        (const float*)d_in[base + 0],  // enc_emb
        (const float*)d_in[base + 1],  // enc_Wih
        (const float*)d_in[base + 2],  // enc_Whh
        (const float*)d_in[base + 3],  // enc_bih
        (const float*)d_in[base + 4],  // enc_bhh
        (const float*)d_in[base + 5],  // dec_emb
        (const float*)d_in[base + 6],  // W_comb
        (const float*)d_in[base + 7],  // b_comb
        (const float*)d_in[base + 8],  // dec_Wih
        (const float*)d_in[base + 9],  // dec_Whh
        (const float*)d_in[base + 10], // dec_bih
        (const float*)d_in[base + 11], // dec_bhh
        (const float*)d_in[base + 12], // W_out
        (const float*)d_in[base + 13], // b_out
        (float*)d_out);
}

// round 17
// speedup vs baseline: 1.0809x; 1.0809x over previous
#include <cuda_runtime.h>
#include <math.h>

#define B_ 32
#define S_ 64
#define T_ 64
#define H_ 256
#define K3 768
#define SOS 1
#define NBLK 128
#define NTHR 256
#define NLINE 32
#define LSTRIDE 64   // 64 u32 = 256B between counter lines

typedef unsigned long long u64;

// pair-packed layout for h/x: element (jj,b) at float index ((jj>>1)*64 + b*2 + (jj&1))
#define HP(jj,b) ((((jj) >> 1) * 64) + ((b) * 2) + ((jj) & 1))

// ---------------- device scratch ----------------
__device__ float g_hT[2][H_ * B_];          // hidden state, pair-packed, double-buffered
__device__ float g_hB[B_ * H_];             // hidden state row-major [b][j]
__device__ float g_xT_all[S_ * H_ * B_];    // encoder inputs [t][jj][b] (scalar layout)
__device__ float g_giE[S_ * K3 * B_];       // precomputed encoder gi [t][k][b]
__device__ float g_xT[H_ * B_];             // decoder x, pair-packed
__device__ float g_EB[B_ * S_ * H_];        // encoder outputs [b][s][j]
__device__ float g_F[B_ * S_ * H_];         // F[b][s][jp] = W_comb2[jp] . enc_outs[s,b]
__device__ float g_c0[H_];
__device__ float g_probs[B_ * T_];
__device__ __align__(128) unsigned int g_bar_count = 0;
__device__ __align__(128) unsigned int g_bar_gen = 0;
__device__ __align__(256) unsigned int g_barA[NLINE * LSTRIDE];
__device__ __align__(256) unsigned int g_xA[NLINE * LSTRIDE];
__device__ __align__(256) unsigned int g_hA[NLINE * LSTRIDE];
__device__ __align__(256) unsigned int g_eA[NLINE * LSTRIDE];

// smem offsets (floats)
#define O_SET   0        // 16640 attn enc_outs TRANSPOSED [jj][s], pitch 65
#define O_SF    16640    // 8192  attn F half
#define O_SH    24832    // 8192  stage (precompute) / sgpH(3072)+sgpI(3072) in loops
#define O_SX    33024    // 8192  stage (precompute) / sgp2(512) in decode (attn)
#define O_SWD   41216    // 6144  dec weights (rows 0-11 gh, 12-23 gi)
#define O_SWE   47360    // 1536  enc weights (6 rows)
#define O_SATT  48896    // 64
#define O_SRED  48960    // 32
#define O_SBH   48992    // 12
#define O_SBI   49004    // 12
#define O_SBE   49016    // 8 (6 used)
#define SMEMF   49024

// fast activations: MUFU-based, error ~1e-6 (budget 1e-3)
__device__ __forceinline__ float fsig(float x) {
    return __fdividef(1.f, 1.f + __expf(-x));
}
__device__ __forceinline__ float ftanh(float x) {
    x = fminf(fmaxf(x, -15.f), 15.f);
    float e2 = __expf(2.f * x);
    return __fdividef(e2 - 1.f, e2 + 1.f);
}

__device__ __forceinline__ float wred(float v) {
#pragma unroll
    for (int o = 16; o > 0; o >>= 1) v += __shfl_xor_sync(0xffffffffu, v, o);
    return v;
}
__device__ __forceinline__ float wmax(float v) {
#pragma unroll
    for (int o = 16; o > 0; o >>= 1) v = fmaxf(v, __shfl_xor_sync(0xffffffffu, v, o));
    return v;
}

// packed fp32x2 FMA: d += a*b elementwise (exact fp32 FMA semantics)
__device__ __forceinline__ void fma2(u64& d, u64 a, u64 b) {
    asm("fma.rn.f32x2 %0, %1, %2, %0;" : "+l"(d) : "l"(a), "l"(b));
}
__device__ __forceinline__ float sum2(u64 v) {
    float x, y;
    asm("mov.b64 {%0,%1}, %2;" : "=f"(x), "=f"(y) : "l"(v));
    return x + y;
}

__device__ __forceinline__ void arrive(unsigned int* arr, int line) {
    asm volatile("red.release.gpu.global.add.u32 [%0], 1;" :: "l"(arr + line * LSTRIDE) : "memory");
}
// executed by FULL warp 0 only: lane l polls line l (acquire polls — no L1-flushing fences)
__device__ __forceinline__ void wait_lines(unsigned int* arr, unsigned int target) {
    if (target == 0) return;
    unsigned int* p = arr + (threadIdx.x & 31) * LSTRIDE;
    for (;;) {
        unsigned int v;
        asm volatile("ld.acquire.gpu.global.u32 %0, [%1];" : "=r"(v) : "l"(p));
        if (__all_sync(0xffffffffu, (int)(v - target) >= 0)) break;
    }
}

// legacy self-cleaning barrier (init phases only; safe across graph replays)
__device__ __forceinline__ void gen_barrier() {
    __syncthreads();
    if (threadIdx.x == 0) {
        unsigned gen;
        asm volatile("ld.acquire.gpu.global.u32 %0, [%1];" : "=r"(gen) : "l"(&g_bar_gen));
        unsigned old;
        asm volatile("atom.release.gpu.global.add.u32 %0, [%1], %2;"
                     : "=r"(old) : "l"(&g_bar_count), "r"(1u) : "memory");
        if (old == NBLK - 1) {
            asm volatile("st.relaxed.gpu.global.u32 [%0], %1;" :: "l"(&g_bar_count), "r"(0u) : "memory");
            asm volatile("st.release.gpu.global.u32 [%0], %1;" :: "l"(&g_bar_gen), "r"(gen + 1u) : "memory");
        } else {
            unsigned cur;
            do { asm volatile("ld.acquire.gpu.global.u32 %0, [%1];" : "=r"(cur) : "l"(&g_bar_gen)); }
            while (cur == gen);
        }
    }
    __syncthreads();
}

// distributed full barrier over all 128 blocks (4 arrivals per line)
__device__ __forceinline__ void dist_barrier(unsigned int nb) {
    __syncthreads();
    if ((threadIdx.x >> 5) == 0) {
        if ((threadIdx.x & 31) == 0) arrive(g_barA, blockIdx.x & 31);
        wait_lines(g_barA, 4u * nb);
    }
    __syncthreads();
}

__device__ __forceinline__ void stage32KB(float* dst, const float* src, int tid) {
    const float4* s4 = (const float4*)src;
    float4* d4 = (float4*)dst;
    for (int i = tid; i < (H_ * B_) / 4; i += NTHR) d4[i] = __ldcg(s4 + i);
}

// legacy dual-row dot for the one-time giE precompute (scalar [jj][b] smem)
__device__ __forceinline__ float2 dot2(const float4* __restrict__ p0, const float4* __restrict__ p1,
                                       const float* __restrict__ sv, int lane, float b0, float b1) {
    float a0a = b0, a0b = 0.f, a1a = b1, a1b = 0.f;
#pragma unroll 8
    for (int q = 0; q < 64; q++) {
        float4 wa = __ldg(p0 + q);
        float4 wb = __ldg(p1 + q);
        int base = q * 128 + lane;
        float h0 = sv[base], h1 = sv[base + 32], h2 = sv[base + 64], h3 = sv[base + 96];
        a0a += wa.x * h0; a0b += wa.y * h1; a0a += wa.z * h2; a0b += wa.w * h3;
        a1a += wb.x * h0; a1b += wb.y * h1; a1a += wb.z * h2; a1b += wb.w * h3;
    }
    return make_float2(a0a + a0b, a1a + a1b);
}

// jj-split dot, packed: warp w owns jj in [w*32, w*32+32); NR rows; lane = b.
template<int NR>
__device__ __forceinline__ void dotGP(const float* __restrict__ sWb,
                                      const float* __restrict__ gsrc,
                                      float* __restrict__ sgp, int w, int lane) {
    const u64* g2 = (const u64*)gsrc;
    u64 hp[16];
#pragma unroll
    for (int i = 0; i < 16; i++) hp[i] = __ldcg(g2 + (w * 16 + i) * 32 + lane);
    const ulonglong2* W2 = (const ulonglong2*)sWb;
    u64 acc[NR];
#pragma unroll
    for (int r = 0; r < NR; r++) acc[r] = 0ull;
#pragma unroll
    for (int r = 0; r < NR; r++) {
#pragma unroll
        for (int q = 0; q < 8; q++) {
            ulonglong2 wv = W2[r * 64 + w * 8 + q];   // broadcast LDS.128
            fma2(acc[r], wv.x, hp[2 * q]);
            fma2(acc[r], wv.y, hp[2 * q + 1]);
        }
    }
#pragma unroll
    for (int r = 0; r < NR; r++) sgp[r * 256 + w * 32 + lane] = sum2(acc[r]);
}

__global__ void __launch_bounds__(NTHR, 1)
seq2seq_kernel(const int* __restrict__ ctx_tok, const int* __restrict__ inp_tok,
               const int* __restrict__ tsamp,
               const float* __restrict__ enc_emb,
               const float* __restrict__ enc_Wih, const float* __restrict__ enc_Whh,
               const float* __restrict__ enc_bih, const float* __restrict__ enc_bhh,
               const float* __restrict__ dec_emb,
               const float* __restrict__ W_comb, const float* __restrict__ b_comb,
               const float* __restrict__ dec_Wih, const float* __restrict__ dec_Whh,
               const float* __restrict__ dec_bih, const float* __restrict__ dec_bhh,
               const float* __restrict__ W_out, const float* __restrict__ b_out,
               float* __restrict__ out)
{
    extern __shared__ float sm[];
    float* sET  = sm + O_SET;       // [jj][s], pitch 65
    float* sF   = sm + O_SF;
    float* sh   = sm + O_SH;        // precompute stage
    float* sgpH = sm + O_SH;        // loop-phase gh partials (3072)
    float* sgpI = sm + O_SH + 3072; // loop-phase gi partials (3072)
    float* sx   = sm + O_SX;
    float* sgp2 = sm + O_SX;        // decode-phase attn score partials (512)
    float* sWd  = sm + O_SWD;
    float* sWe  = sm + O_SWE;
    float* satt = sm + O_SATT;
    float* sred = sm + O_SRED;
    float* sbh  = sm + O_SBH;
    float* sbi  = sm + O_SBI;
    float* sbe  = sm + O_SBE;

    const int tid  = threadIdx.x;
    const int lane = tid & 31;
    const int w    = tid >> 5;       // warp 0..7
    const int bx   = blockIdx.x;

    // ---------------- init (parallel) ----------------
    for (int i = bx * NTHR + tid; i < NLINE * LSTRIDE; i += NBLK * NTHR) {
        g_barA[i] = 0u; g_xA[i] = 0u; g_hA[i] = 0u; g_eA[i] = 0u;
    }
    for (int i = bx * NTHR + tid; i < H_ * B_; i += NBLK * NTHR) g_hT[0][i] = 0.f;

    for (int i = bx * NTHR + tid; i < S_ * B_ * H_; i += NBLK * NTHR) {
        int jj = i & (H_ - 1);
        int tb = i >> 8;
        int b  = tb & (B_ - 1);
        int t  = tb >> 5;
        int tok = ctx_tok[b * S_ + t];
        g_xT_all[(t * H_ + jj) * B_ + b] = enc_emb[(size_t)tok * H_ + jj];
    }
    {   // c0[j'] = b_comb[j'] + W_comb[j', 0:H] . dec_emb[SOS]   (blocks 0..31)
        int gw = bx * 8 + w;
        if (gw < H_) {
            float s = 0.f;
#pragma unroll
            for (int m = 0; m < 8; m++) {
                int jj = lane + 32 * m;
                s += __ldg(&W_comb[(size_t)gw * (2 * H_) + jj]) * __ldg(&dec_emb[SOS * H_ + jj]);
            }
            s = wred(s);
            if (lane == 0) g_c0[gw] = s + b_comb[gw];
        }
    }
    gen_barrier();

    // ---------------- encoder gi precompute (one-time, parallel) ----------------
    {
        const int t  = bx >> 1;
        const int kh = (bx & 1) * 384;
        stage32KB(sh, g_xT_all + (size_t)t * H_ * B_, tid);
        __syncthreads();
        for (int i = 0; i < 24; i++) {
            int k0 = kh + w * 48 + 2 * i;
            int k1 = k0 + 1;
            const float4* pA = (const float4*)(enc_Wih + (size_t)k0 * H_);
            const float4* pB = (const float4*)(enc_Wih + (size_t)k1 * H_);
            float2 r = dot2(pA, pB, sh, lane, enc_bih[k0], enc_bih[k1]);
            g_giE[((size_t)t * K3 + k0) * B_ + lane] = r.x;
            g_giE[((size_t)t * K3 + k1) * B_ + lane] = r.y;
        }
    }
    gen_barrier();

    // ---------------- encoder weight preload (6 rows: r = g*2+p) ----------------
    {
        float4* d = (float4*)sWe;
        for (int i = tid; i < 6 * 64; i += NTHR) {
            int r = i >> 6, q = i & 63;
            int k = (r >> 1) * H_ + bx * 2 + (r & 1);
            d[i] = __ldg(((const float4*)(enc_Whh + (size_t)k * H_)) + q);
        }
        if (tid < 6) sbe[tid] = enc_bhh[(tid >> 1) * H_ + bx * 2 + (tid & 1)];
    }
    __syncthreads();

    int buf = 0;
    float hprevE = 0.f;   // register-carried h_old (encoder, w<2)

    // ---------------- encoder: 64 steps ----------------
    for (int t = 0; t < S_; t++) {
        float gi0 = 0.f, gi1 = 0.f, gi2 = 0.f;
        if (w < 2) {
            const float* gp = g_giE + ((size_t)t * K3 + (bx * 2 + w)) * B_ + lane;
            gi0 = __ldcg(gp);
            gi1 = __ldcg(gp + 256 * B_);
            gi2 = __ldcg(gp + 512 * B_);
        }
        dotGP<6>(sWe, g_hT[buf], sgpH, w, lane);
        __syncthreads();

        if (w < 2) {   // fused reduce + combine: rows w (r), 2+w (z), 4+w (n)
            int j = bx * 2 + w;
            float ghr = sbe[w], ghz = sbe[2 + w], ghn = sbe[4 + w];
#pragma unroll
            for (int u = 0; u < 8; u++) {
                ghr += sgpH[w * 256 + u * 32 + lane];
                ghz += sgpH[(2 + w) * 256 + u * 32 + lane];
                ghn += sgpH[(4 + w) * 256 + u * 32 + lane];
            }
            float r = fsig(gi0 + ghr);
            float z = fsig(gi1 + ghz);
            float n = ftanh(gi2 + r * ghn);
            float hn = (1.f - z) * n + z * hprevE;
            hprevE = hn;
            g_hT[buf ^ 1][HP(j, lane)] = hn;
            g_EB[((size_t)lane * S_ + t) * H_ + j] = hn;
            if (t == S_ - 1) g_hB[lane * H_ + j] = hn;
            __syncwarp();
            if (lane == 0) arrive(g_eA, bx & 31);
        }
        if (w == 0) wait_lines(g_eA, 8u * (unsigned)(t + 1));
        __syncthreads();
        buf ^= 1;
        if (bx >= 64) {   // attn blocks progressively stage enc_outs TRANSPOSED: sET[jj][t]
            int b = (bx - 64) >> 1;
            sET[tid * 65 + t] = __ldcg(&g_EB[((size_t)b * S_ + t) * H_ + tid]);
        }
    }

    // ---------------- F precompute: F[b][s][jp] = W_comb2[jp] . enc_outs[s,b] ----------------
    {
        int jpT = bx & 15, bsT = bx >> 4;
        int jp0 = jpT * 16, p0 = bsT * 256;
        float4* wt = (float4*)sx;   // 16 rows x 64 quads
        for (int i = tid; i < 16 * 64; i += NTHR) {
            int r = i >> 6, q = i & 63;
            wt[i] = __ldg(((const float4*)(W_comb + (size_t)(jp0 + r) * (2 * H_) + H_)) + q);
        }
        __syncthreads();
        int jpl = tid >> 4, pl = tid & 15;
        for (int i = 0; i < 16; i++) {
            int p = p0 + i * 16 + pl;
            int b = p >> 6, s = p & 63;
            const float4* e4 = (const float4*)(g_EB + ((size_t)b * S_ + s) * H_);
            float a0 = 0.f, a1 = 0.f;
#pragma unroll 8
            for (int q = 0; q < 64; q++) {
                float4 e = __ldcg(e4 + q);
                float4 wv = wt[jpl * 64 + q];
                a0 += e.x * wv.x + e.z * wv.z;
                a1 += e.y * wv.y + e.w * wv.w;
            }
            g_F[((size_t)b * S_ + s) * H_ + jp0 + jpl] = a0 + a1;
        }
    }
    gen_barrier();

    // ---------------- decode-phase staging ----------------
    float hprevD = 0.f;
    float c0reg = 0.f;
    if (bx >= 64) {   // attn: stage F half [s][jp_local]; cache c0 in register
        int bxa = bx - 64, b = bxa >> 1, half = bxa & 1;
        float4* dst = (float4*)sF;
        for (int i = tid; i < 64 * 32; i += NTHR) {
            int s = i >> 5, q = i & 31;
            dst[i] = __ldcg(((const float4*)(g_F + ((size_t)b * S_ + s) * H_ + half * 128)) + q);
        }
        if (tid < 128) c0reg = __ldg(&g_c0[half * 128 + tid]);
    } else {          // GRU: stage decoder weights (24 rows) + biases, seed hold register
        float4* d = (float4*)sWd;
        for (int i = tid; i < 24 * 64; i += NTHR) {
            int r = i >> 6, q = i & 63;
            int rr = (r < 12) ? r : (r - 12);
            int k = (rr >> 2) * H_ + bx * 4 + (rr & 3);
            const float* src = (r < 12) ? dec_Whh : dec_Wih;
            d[i] = __ldg(((const float4*)(src + (size_t)k * H_)) + q);
        }
        if (tid < 12) {
            int k = (tid >> 2) * H_ + bx * 4 + (tid & 3);
            sbh[tid] = dec_bhh[k];
            sbi[tid] = dec_bih[k];
        }
        if (w < 4) hprevD = __ldcg(&g_hT[0][HP(bx * 4 + w, lane)]);   // h_enc
    }
    __syncthreads();

    // ---------------- decoder: 64 steps, 2 producer flags each ----------------
    for (int t = 0; t < T_; t++) {
        // prob prefetch: W_out row for token t-1, independent of h (overlaps h-wait)
        float wrow[8]; int tokPrev = 0;
        const bool probWarp = (bx >= 64) && (((bx - 64) & 1) == 1) && (w == 4);
        if (probWarp && t > 0) {
            int b = (bx - 64) >> 1;
            tokPrev = __ldg(&inp_tok[b * T_ + (t - 1)]);
#pragma unroll
            for (int m = 0; m < 8; m++) wrow[m] = __ldg(&W_out[(size_t)tokPrev * H_ + lane + 32 * m]);
        }

        if (w == 0) wait_lines(g_hA, 8u * (unsigned)t);
        __syncthreads();

        if (bx < 64) {
            // ---- GRU path ----
            dotGP<12>(sWd, g_hT[buf], sgpH, w, lane);       // gh partials
            if (w == 0) wait_lines(g_xA, 8u * (unsigned)(t + 1));
            __syncthreads();
            dotGP<12>(sWd + 12 * H_, g_xT, sgpI, w, lane);  // gi partials
            __syncthreads();
            if (w < 4) {   // fused reduce + combine: rows w (r), 4+w (z), 8+w (n)
                int j = bx * 4 + w;
                float ghr = sbh[w], ghz = sbh[4 + w], ghn = sbh[8 + w];
                float gir = sbi[w], giz = sbi[4 + w], gin = sbi[8 + w];
#pragma unroll
                for (int u = 0; u < 8; u++) {
                    int o = u * 32 + lane;
                    ghr += sgpH[w * 256 + o];
                    ghz += sgpH[(4 + w) * 256 + o];
                    ghn += sgpH[(8 + w) * 256 + o];
                    gir += sgpI[w * 256 + o];
                    giz += sgpI[(4 + w) * 256 + o];
                    gin += sgpI[(8 + w) * 256 + o];
                }
                float r = fsig(gir + ghr);
                float z = fsig(giz + ghz);
                float n = ftanh(gin + r * ghn);
                float hn = (1.f - z) * n + z * hprevD;
                hprevD = hn;
                g_hT[buf ^ 1][HP(j, lane)] = hn;
                g_hB[lane * H_ + j] = hn;
                __syncwarp();
                if (lane == 0) arrive(g_hA, bx & 31);
            }
        } else {
            // ---- attention path: b = (bx-64)>>1, half = (bx-64)&1 ----
            const int bxa = bx - 64, b = bxa >> 1, half = bxa & 1;
            // transposed scores: warp w owns jj in [32w, 32w+32); lane owns s=lane, s=lane+32
            {
                const int jj0 = w * 32;
                float hval = __ldcg(&g_hB[b * H_ + jj0 + lane]);
                const float* et = sET + jj0 * 65 + lane;
                float p0 = 0.f, p1 = 0.f;
#pragma unroll
                for (int i = 0; i < 32; i++) {
                    float hv = __shfl_sync(0xffffffffu, hval, i);
                    p0 += hv * et[i * 65];
                    p1 += hv * et[i * 65 + 32];
                }
                sgp2[w * 64 + lane] = p0;
                sgp2[w * 64 + 32 + lane] = p1;
            }
            __syncthreads();
            if (w == 0) {   // fused cross-warp reduce + softmax (values in registers)
                float v0 = 0.f, v1 = 0.f;
#pragma unroll
                for (int u = 0; u < 8; u++) { v0 += sgp2[u * 64 + lane]; v1 += sgp2[u * 64 + 32 + lane]; }
                float mx = wmax(fmaxf(v0, v1));
                float e0 = __expf(v0 - mx), e1 = __expf(v1 - mx);
                float rs = __fdividef(1.f, wred(e0 + e1));
                satt[lane] = e0 * rs; satt[lane + 32] = e1 * rs;
            }
            __syncthreads();
            // x[jp] = relu(c0[jp] + sum_s attn[s] * F[s][jp]); warps 0-3
            if (tid < 128) {
                int jp = half * 128 + tid;
                const float* fp = sF + tid;
                float a0 = c0reg, a1 = 0.f, a2 = 0.f, a3 = 0.f;
#pragma unroll
                for (int s = 0; s < S_; s += 4) {
                    a0 += satt[s]     * fp[s * 128];
                    a1 += satt[s + 1] * fp[(s + 1) * 128];
                    a2 += satt[s + 2] * fp[(s + 2) * 128];
                    a3 += satt[s + 3] * fp[(s + 3) * 128];
                }
                float acc = (a0 + a1) + (a2 + a3);
                g_xT[HP(jp, b)] = acc > 0.f ? acc : 0.f;
                __syncwarp();
                if (lane == 0) arrive(g_xA, bxa & 31);
            } else if (probWarp && t > 0) {
                // prob for step t-1, concurrent with x compute (off critical path)
                float p = 0.f;
#pragma unroll
                for (int m = 0; m < 8; m++) p += __ldcg(&g_hB[b * H_ + lane + 32 * m]) * wrow[m];
                p = wred(p);
                if (lane == 0) g_probs[b * T_ + (t - 1)] = fsig(p + __ldg(&b_out[tokPrev]));
            }
        }
        buf ^= 1;
    }

    // ---------------- final-step prob ----------------
    if (bx >= 64 && ((bx - 64) & 1) == 1) {
        const int b = (bx - 64) >> 1;
        if (w == 0) {
            wait_lines(g_hA, 8u * (unsigned)T_);
            int tok = __ldg(&inp_tok[b * T_ + (T_ - 1)]);
            float p = 0.f;
#pragma unroll
            for (int m = 0; m < 8; m++)
                p += __ldcg(&g_hB[b * H_ + lane + 32 * m]) * __ldg(&W_out[(size_t)tok * H_ + lane + 32 * m]);
            p = wred(p);
            if (lane == 0) g_probs[b * T_ + (T_ - 1)] = fsig(p + b_out[tok]);
        }
    }
    dist_barrier(1u);

    // ---------------- outputs ----------------
    for (int i = bx * NTHR + tid; i < B_ * T_; i += NBLK * NTHR) out[1 + i] = __ldcg(g_probs + i);
    if (bx == 0) {
        float tv = tsamp ? (float)(*tsamp) : 1.0f;
        float acc = 0.f;
        for (int i = tid; i < B_ * T_; i += NTHR) {
            float p  = __ldcg(g_probs + i);
            float lp = fmaxf(logf(p), -100.f);
            float l1 = fmaxf(log1pf(-p), -100.f);
            acc += tv * lp + (1.f - tv) * l1;
        }
        acc = wred(acc);
        if (lane == 0) sred[w] = acc;
        __syncthreads();
        if (tid == 0) {
            float s = 0.f;
            for (int u = 0; u < 8; u++) s += sred[u];
            out[0] = -s / (float)(B_ * T_);
        }
    }
}

extern "C" void kernel_launch(void* const* d_in, const int* in_sizes, int n_in,
                              void* d_out, int out_size) {
    (void)in_sizes; (void)out_size;
    const size_t smem = SMEMF * sizeof(float);   // 196,096 B
    cudaFuncSetAttribute(seq2seq_kernel, cudaFuncAttributeMaxDynamicSharedMemorySize, (int)smem);

    int base = (n_in >= 17) ? 3 : 2;
    const int* ts = (n_in >= 17) ? (const int*)d_in[2] : nullptr;

    seq2seq_kernel<<<NBLK, NTHR, smem>>>(
        (const int*)d_in[0], (const int*)d_in[1], ts,
        (const float*)d_in[base + 0],  // enc_emb
        (const float*)d_in[base + 1],  // enc_Wih
        (const float*)d_in[base + 2],  // enc_Whh
        (const float*)d_in[base + 3],  // enc_bih
        (const float*)d_in[base + 4],  // enc_bhh
        (const float*)d_in[base + 5],  // dec_emb
        (const float*)d_in[base + 6],  // W_comb
        (const float*)d_in[base + 7],  // b_comb
        (const float*)d_in[base + 8],  // dec_Wih
        (const float*)d_in[base + 9],  // dec_Whh
        (const float*)d_in[base + 10], // dec_bih
        (const float*)d_in[base + 11], // dec_bhh
        (const float*)d_in[base + 12], // W_out
        (const float*)d_in[base + 13], // b_out
        (float*)d_out);
}